// round 6
// baseline (speedup 1.0000x reference)
#include <cuda_runtime.h>
#include <cstdint>

namespace {
constexpr int  Bc   = 8;
constexpr int  CIN  = 16;
constexpr int  COUT = 16;
constexpr int  KS   = 4;
constexpr long long NN = 524288;   // N
constexpr int  THREADS = 128;
constexpr int  TOK_PER_CTA = 512;  // 64 token-threads x 8 tokens
constexpr int  BLKS_PER_B  = (int)(NN / TOK_PER_CTA);  // 1024
constexpr int  GRID = Bc * BLKS_PER_B;                 // 8192
}

// Packed fp32x2 FMA / MUL (PTX-only; ptxas never auto-fuses to FFMA2)
__device__ __forceinline__ unsigned long long fma2(unsigned long long a,
                                                   unsigned long long b,
                                                   unsigned long long c) {
    unsigned long long d;
    asm("fma.rn.f32x2 %0, %1, %2, %3;" : "=l"(d) : "l"(a), "l"(b), "l"(c));
    return d;
}
__device__ __forceinline__ unsigned long long mul2(unsigned long long a,
                                                   unsigned long long b) {
    unsigned long long d;
    asm("mul.rn.f32x2 %0, %1, %2;" : "=l"(d) : "l"(a), "l"(b));
    return d;
}

// R6 (= R5, never ran due to infra failure): 8 tokens x 8 outputs per thread.
// Warps 0-1 compute o=0..7, warps 2-3 o=8..15 for the SAME 512 tokens (second
// read of x/s hits L1). Doubles the fma:LDS ratio vs R3 (128 fma2 per 32
// LDS.64 per channel) and doubles the c-iter body length so the one-deep x
// prefetch actually covers DRAM latency.
__global__ __launch_bounds__(THREADS, 4)
void tconv_f32x2_kernel(const float* __restrict__ inp,   // [B, CIN, N]
                        const float* __restrict__ wgt,   // [COUT, KS, CIN]
                        const float* __restrict__ att,   // [B, KS, N]
                        float* __restrict__ out)         // [B, COUT, N]
{
    // wdup[h][c][k][o']: duplicated (w,w) u64; all inner reads warp-uniform
    // (broadcast LDS.64, conflict-free). 1024 entries = 8KB.
    __shared__ unsigned long long wdup[2 * CIN * KS * 8];
    const int tid = threadIdx.x;
    #pragma unroll
    for (int i = tid; i < 2 * CIN * KS * 8; i += THREADS) {
        int h = i >> 9, c = (i >> 5) & 15, k = (i >> 3) & 3, o = i & 7;
        unsigned int bits = __float_as_uint(wgt[((h * 8 + o) * KS + k) * CIN + c]);
        wdup[i] = ((unsigned long long)bits << 32) | bits;
    }
    __syncthreads();

    const int h  = tid >> 6;          // output half (warp-uniform)
    const int tt = tid & 63;          // token-thread within CTA
    const int b  = blockIdx.x >> 10;  // BLKS_PER_B = 1024
    const long long n0 = ((long long)(blockIdx.x & 1023) << 9) + (long long)tt * 8;

    const float* xb = inp + (long long)b * CIN * NN + n0;
    const float* sb = att + (long long)b * KS  * NN + n0;

    // Score taps, 2 quads each (16 u64 = 32 regs).
    unsigned long long s0l[KS], s0h[KS], s1l[KS], s1h[KS];
    #pragma unroll
    for (int k = 0; k < KS; k++) {
        ulonglong2 v0 = *reinterpret_cast<const ulonglong2*>(sb + (long long)k * NN);
        ulonglong2 v1 = *reinterpret_cast<const ulonglong2*>(sb + (long long)k * NN + 4);
        s0l[k] = v0.x; s0h[k] = v0.y; s1l[k] = v1.x; s1h[k] = v1.y;
    }

    // Accumulators: 8 outputs x 2 quads x (lo,hi) = 32 u64 = 64 regs.
    unsigned long long a0l[8], a0h[8], a1l[8], a1h[8];
    #pragma unroll
    for (int o = 0; o < 8; o++) { a0l[o] = 0; a0h[o] = 0; a1l[o] = 0; a1h[o] = 0; }

    // Prefetch channel 0 (2 quads = 4 u64).
    ulonglong2 xn0 = *reinterpret_cast<const ulonglong2*>(xb);
    ulonglong2 xn1 = *reinterpret_cast<const ulonglong2*>(xb + 4);

    const unsigned long long* wh = &wdup[h * (CIN * KS * 8)];

    #pragma unroll 1
    for (int c = 0; c < CIN; c++) {
        ulonglong2 x0 = xn0, x1 = xn1;
        int cn = c + 1 < CIN ? c + 1 : CIN - 1;   // clamped prefetch
        xn0 = *reinterpret_cast<const ulonglong2*>(xb + (long long)cn * NN);
        xn1 = *reinterpret_cast<const ulonglong2*>(xb + (long long)cn * NN + 4);

        const unsigned long long* wc = wh + c * (KS * 8);
        #pragma unroll
        for (int k = 0; k < KS; k++) {
            // z = x * s[k] for both quads (4 mul2, 8 regs live)
            unsigned long long z0l = mul2(x0.x, s0l[k]);
            unsigned long long z0h = mul2(x0.y, s0h[k]);
            unsigned long long z1l = mul2(x1.x, s1l[k]);
            unsigned long long z1h = mul2(x1.y, s1h[k]);
            const unsigned long long* wk = wc + k * 8;
            #pragma unroll
            for (int o = 0; o < 8; o++) {
                unsigned long long w = wk[o];          // broadcast LDS.64
                a0l[o] = fma2(w, z0l, a0l[o]);
                a0h[o] = fma2(w, z0h, a0h[o]);
                a1l[o] = fma2(w, z1l, a1l[o]);
                a1h[o] = fma2(w, z1h, a1h[o]);
            }
        }
    }

    float* ob = out + (long long)b * COUT * NN + (long long)(h * 8) * NN + n0;
    #pragma unroll
    for (int o = 0; o < 8; o++) {
        ulonglong2 r0; r0.x = a0l[o]; r0.y = a0h[o];
        ulonglong2 r1; r1.x = a1l[o]; r1.y = a1h[o];
        *reinterpret_cast<ulonglong2*>(ob + (long long)o * NN)     = r0;
        *reinterpret_cast<ulonglong2*>(ob + (long long)o * NN + 4) = r1;
    }
}

extern "C" void kernel_launch(void* const* d_in, const int* in_sizes, int n_in,
                              void* d_out, int out_size)
{
    const float* inp = (const float*)d_in[0];   // input  [8,16,524288]
    const float* wgt = (const float*)d_in[1];   // weight [16,4,16]
    const float* att = (const float*)d_in[2];   // attention_score [8,4,524288]
    float* out = (float*)d_out;                 // [8,16,524288]

    tconv_f32x2_kernel<<<GRID, THREADS>>>(inp, wgt, att, out);
}

// round 7
// speedup vs baseline: 2.3154x; 2.3154x over previous
#include <cuda_runtime.h>
#include <cstdint>

namespace {
constexpr int  CIN  = 16;
constexpr int  COUT = 16;
constexpr int  KS   = 4;
constexpr long long NN = 524288;
constexpr int  THREADS = 128;                 // 4 warps
constexpr int  TOK     = 128;                 // tokens per CTA-iter
constexpr int  TILES   = (int)(8 * NN / TOK); // 32768
constexpr int  GRID    = 8192;                // 4 tiles per CTA
constexpr int  XPAD    = 18;                  // f32 words per token row (even, conflict-safe)
constexpr int  SPAD    = 6;                   // u64 per token row (16B-aligned rows)
constexpr int  OPAD    = 132;                 // output bounce row pad
}

// ---- packed f32x2 mul (PTX-only) ----
__device__ __forceinline__ unsigned long long mul2(unsigned long long a,
                                                   unsigned long long b) {
    unsigned long long d;
    asm("mul.rn.f32x2 %0, %1, %2;" : "=l"(d) : "l"(a), "l"(b));
    return d;
}
// pack two f32 -> bf16x2 with round-to-nearest. First asm operand = HIGH half.
__device__ __forceinline__ uint32_t packbf(float hi, float lo) {
    uint32_t r;
    asm("cvt.rn.bf16x2.f32 %0, %1, %2;" : "=r"(r) : "f"(hi), "f"(lo));
    return r;
}
// m16n8k16 row.col bf16 MMA, D=C (accumulate in place)
__device__ __forceinline__ void mma_bf16(float* d, uint32_t a0, uint32_t a1,
                                         uint32_t a2, uint32_t a3,
                                         uint32_t b0, uint32_t b1) {
    asm volatile(
        "mma.sync.aligned.m16n8k16.row.col.f32.bf16.bf16.f32 "
        "{%0,%1,%2,%3}, {%4,%5,%6,%7}, {%8,%9}, {%0,%1,%2,%3};"
        : "+f"(d[0]), "+f"(d[1]), "+f"(d[2]), "+f"(d[3])
        : "r"(a0), "r"(a1), "r"(a2), "r"(a3), "r"(b0), "r"(b1));
}
// split packed-f32x2 z into (zh_pack bf16x2, zl_pack bf16x2)
__device__ __forceinline__ void split_z(unsigned long long z,
                                        uint32_t& zh, uint32_t& zl) {
    float z0 = __uint_as_float((uint32_t)z);          // element 0 (low addr)
    float z1 = __uint_as_float((uint32_t)(z >> 32));  // element 1
    zh = packbf(z1, z0);
    float h0 = __uint_as_float(zh << 16);
    float h1 = __uint_as_float(zh & 0xFFFF0000u);
    zl = packbf(z1 - h1, z0 - h0);
}

__global__ __launch_bounds__(THREADS)
void tconv_mma_kernel(const float* __restrict__ inp,   // [B, CIN, N]
                      const float* __restrict__ wgt,   // [COUT, KS, CIN]
                      const float* __restrict__ att,   // [B, KS, N]
                      float* __restrict__ out)         // [B, COUT, N]
{
    __shared__ float              xs[TOK * XPAD];      // x staged [tok][c]
    __shared__ unsigned long long sd[TOK * SPAD];      // s staged [tok][k], (s,s) dup
    __shared__ float              od[COUT * OPAD];     // output bounce [o][tok]

    const int tid  = threadIdx.x;
    const int lane = tid & 31;
    const int w    = tid >> 5;
    const int cq   = lane & 3;      // thread-in-group (cols)
    const int r    = lane >> 2;     // group id (rows / n-index)

    // ---- build W fragments in registers (col-major B frag, split hi/lo) ----
    // B[kc][o] = wgt[(o*KS + kt)*CIN + kr],  kc = kt*16 + kr
    uint32_t bh[2][KS][2], bl[2][KS][2];
    #pragma unroll
    for (int h = 0; h < 2; h++) {
        int o = 8 * h + r;
        #pragma unroll
        for (int kt = 0; kt < KS; kt++) {
            int base = (o * KS + kt) * CIN;
            #pragma unroll
            for (int p = 0; p < 2; p++) {              // p=0: kr=2cq, p=1: kr=2cq+8
                float wa = wgt[base + 2 * cq + 8 * p];
                float wb = wgt[base + 2 * cq + 8 * p + 1];
                uint32_t hp = packbf(wb, wa);
                float ha = __uint_as_float(hp << 16);
                float hb = __uint_as_float(hp & 0xFFFF0000u);
                bh[h][kt][p] = hp;
                bl[h][kt][p] = packbf(wb - hb, wa - ha);
            }
        }
    }

    // ---- prologue: load tile 0 into regs ----
    float rx[CIN], rs[KS];
    {
        int t = blockIdx.x;
        long long b = t >> 12, n = ((long long)(t & 4095) << 7) + tid;
        const float* xb = inp + b * CIN * NN + n;
        const float* sb = att + b * KS * NN + n;
        #pragma unroll
        for (int c = 0; c < CIN; c++) rx[c] = xb[(long long)c * NN];
        #pragma unroll
        for (int k = 0; k < KS; k++)  rs[k] = sb[(long long)k * NN];
    }

    for (int i = 0; i < TILES / GRID; i++) {
        const int t = blockIdx.x + i * GRID;

        // stage tile i
        #pragma unroll
        for (int c = 0; c < CIN; c++) xs[tid * XPAD + c] = rx[c];
        #pragma unroll
        for (int k = 0; k < KS; k++) {
            uint32_t bits = __float_as_uint(rs[k]);
            sd[tid * SPAD + k] = ((unsigned long long)bits << 32) | bits;
        }
        __syncthreads();

        // prefetch tile i+1
        if (i + 1 < TILES / GRID) {
            int tn = t + GRID;
            long long b = tn >> 12, n = ((long long)(tn & 4095) << 7) + tid;
            const float* xb = inp + b * CIN * NN + n;
            const float* sb = att + b * KS * NN + n;
            #pragma unroll
            for (int c = 0; c < CIN; c++) rx[c] = xb[(long long)c * NN];
            #pragma unroll
            for (int k = 0; k < KS; k++)  rs[k] = sb[(long long)k * NN];
        }

        // ---- compute: each warp does 2 m16-tiles (32 tokens) ----
        #pragma unroll
        for (int mt = 0; mt < 2; mt++) {
            const int tb = w * 32 + mt * 16;
            const int tokA = tb + r, tokB = tb + r + 8;

            // x pairs: cols (2cq,2cq+1) and (2cq+8,2cq+9) for both token rows
            unsigned long long xA0 = *reinterpret_cast<const unsigned long long*>(
                xs + tokA * XPAD + 2 * cq);
            unsigned long long xA1 = *reinterpret_cast<const unsigned long long*>(
                xs + tokA * XPAD + 2 * cq + 8);
            unsigned long long xB0 = *reinterpret_cast<const unsigned long long*>(
                xs + tokB * XPAD + 2 * cq);
            unsigned long long xB1 = *reinterpret_cast<const unsigned long long*>(
                xs + tokB * XPAD + 2 * cq + 8);
            // s duplicated pairs for both token rows
            ulonglong2 sA01 = *reinterpret_cast<const ulonglong2*>(sd + tokA * SPAD);
            ulonglong2 sA23 = *reinterpret_cast<const ulonglong2*>(sd + tokA * SPAD + 2);
            ulonglong2 sB01 = *reinterpret_cast<const ulonglong2*>(sd + tokB * SPAD);
            ulonglong2 sB23 = *reinterpret_cast<const ulonglong2*>(sd + tokB * SPAD + 2);
            unsigned long long sA[KS] = {sA01.x, sA01.y, sA23.x, sA23.y};
            unsigned long long sB[KS] = {sB01.x, sB01.y, sB23.x, sB23.y};

            float d0[4] = {0.f, 0.f, 0.f, 0.f};
            float d1[4] = {0.f, 0.f, 0.f, 0.f};

            #pragma unroll
            for (int kt = 0; kt < KS; kt++) {
                // z = x * s[kt]  (A-frag: a0=(r,2c..), a1=(r+8,2c..), a2=(r,2c+8..), a3=(r+8,2c+8..))
                uint32_t ah0, al0, ah1, al1, ah2, al2, ah3, al3;
                split_z(mul2(xA0, sA[kt]), ah0, al0);
                split_z(mul2(xB0, sB[kt]), ah1, al1);
                split_z(mul2(xA1, sA[kt]), ah2, al2);
                split_z(mul2(xB1, sB[kt]), ah3, al3);

                mma_bf16(d0, ah0, ah1, ah2, ah3, bh[0][kt][0], bh[0][kt][1]);
                mma_bf16(d1, ah0, ah1, ah2, ah3, bh[1][kt][0], bh[1][kt][1]);
                mma_bf16(d0, al0, al1, al2, al3, bh[0][kt][0], bh[0][kt][1]);
                mma_bf16(d1, al0, al1, al2, al3, bh[1][kt][0], bh[1][kt][1]);
                mma_bf16(d0, ah0, ah1, ah2, ah3, bl[0][kt][0], bl[0][kt][1]);
                mma_bf16(d1, ah0, ah1, ah2, ah3, bl[1][kt][0], bl[1][kt][1]);
            }

            // epilogue: D -> od[o][tok]   d: (r,2c),(r,2c+1),(r+8,2c),(r+8,2c+1)
            od[(2 * cq + 0) * OPAD + tokA] = d0[0];
            od[(2 * cq + 1) * OPAD + tokA] = d0[1];
            od[(2 * cq + 0) * OPAD + tokB] = d0[2];
            od[(2 * cq + 1) * OPAD + tokB] = d0[3];
            od[(8 + 2 * cq + 0) * OPAD + tokA] = d1[0];
            od[(8 + 2 * cq + 1) * OPAD + tokA] = d1[1];
            od[(8 + 2 * cq + 0) * OPAD + tokB] = d1[2];
            od[(8 + 2 * cq + 1) * OPAD + tokB] = d1[3];
        }
        __syncthreads();

        // coalesced write-out
        {
            long long b = t >> 12, n = ((long long)(t & 4095) << 7) + tid;
            float* ob = out + b * COUT * NN + n;
            #pragma unroll
            for (int o = 0; o < COUT; o++)
                ob[(long long)o * NN] = od[o * OPAD + tid];
        }
        __syncthreads();
    }
}

extern "C" void kernel_launch(void* const* d_in, const int* in_sizes, int n_in,
                              void* d_out, int out_size)
{
    const float* inp = (const float*)d_in[0];   // input  [8,16,524288]
    const float* wgt = (const float*)d_in[1];   // weight [16,4,16]
    const float* att = (const float*)d_in[2];   // attention_score [8,4,524288]
    float* out = (float*)d_out;                 // [8,16,524288]

    tconv_mma_kernel<<<GRID, THREADS>>>(inp, wgt, att, out);
}

// round 8
// speedup vs baseline: 2.3906x; 1.0325x over previous
#include <cuda_runtime.h>
#include <cstdint>

namespace {
constexpr int  CIN  = 16;
constexpr int  COUT = 16;
constexpr int  KS   = 4;
constexpr long long NN = 524288;
constexpr int  THREADS = 128;                 // 4 warps
constexpr int  TOK     = 128;                 // tokens per CTA-iter
constexpr int  TILES   = (int)(8 * NN / TOK); // 32768
constexpr int  GRID    = 8192;                // 4 tiles per CTA
constexpr int  PADT    = 132;                 // staging row pitch (floats)
constexpr int  OPAD    = 132;                 // output bounce row pitch
}

// ---- packed f32x2 mul (PTX-only) ----
__device__ __forceinline__ unsigned long long mul2(unsigned long long a,
                                                   unsigned long long b) {
    unsigned long long d;
    asm("mul.rn.f32x2 %0, %1, %2;" : "=l"(d) : "l"(a), "l"(b));
    return d;
}
// pack two f32 into u64 (element0 = lo)
__device__ __forceinline__ unsigned long long pack2(float lo, float hi) {
    unsigned long long d;
    asm("mov.b64 %0, {%1, %2};" : "=l"(d) : "f"(lo), "f"(hi));
    return d;
}
// pack two f32 -> bf16x2 round-to-nearest. First operand = HIGH half.
__device__ __forceinline__ uint32_t packbf(float hi, float lo) {
    uint32_t r;
    asm("cvt.rn.bf16x2.f32 %0, %1, %2;" : "=r"(r) : "f"(hi), "f"(lo));
    return r;
}
// m16n8k16 row.col bf16 MMA, accumulate in place
__device__ __forceinline__ void mma_bf16(float* d, uint32_t a0, uint32_t a1,
                                         uint32_t a2, uint32_t a3,
                                         uint32_t b0, uint32_t b1) {
    asm volatile(
        "mma.sync.aligned.m16n8k16.row.col.f32.bf16.bf16.f32 "
        "{%0,%1,%2,%3}, {%4,%5,%6,%7}, {%8,%9}, {%0,%1,%2,%3};"
        : "+f"(d[0]), "+f"(d[1]), "+f"(d[2]), "+f"(d[3])
        : "r"(a0), "r"(a1), "r"(a2), "r"(a3), "r"(b0), "r"(b1));
}
// split packed-f32x2 z into (zh bf16x2, zl bf16x2)
__device__ __forceinline__ void split_z(unsigned long long z,
                                        uint32_t& zh, uint32_t& zl) {
    float z0 = __uint_as_float((uint32_t)z);
    float z1 = __uint_as_float((uint32_t)(z >> 32));
    zh = packbf(z1, z0);
    float h0 = __uint_as_float(zh << 16);
    float h1 = __uint_as_float(zh & 0xFFFF0000u);
    zl = packbf(z1 - h1, z0 - h0);
}

__global__ __launch_bounds__(THREADS)
void tconv_mma_kernel(const float* __restrict__ inp,   // [B, CIN, N]
                      const float* __restrict__ wgt,   // [COUT, KS, CIN]
                      const float* __restrict__ att,   // [B, KS, N]
                      float* __restrict__ out)         // [B, COUT, N]
{
    __shared__ __align__(16) float xs[CIN * PADT];   // x staged [c][tok]
    __shared__ __align__(16) float ss[KS * PADT];    // s staged [k][tok]
    __shared__ float od[COUT * OPAD];                // output bounce [o][tok]

    const int tid  = threadIdx.x;
    const int lane = tid & 31;
    const int w    = tid >> 5;
    const int cq   = lane & 3;      // col-thread
    const int r    = lane >> 2;     // row/group
    const int c0   = tid >> 5;      // staging: channel-group / k id
    const int q    = lane;          // staging: token quad

    // ---- build W fragments in registers (col-major B frag, split hi/lo) ----
    uint32_t bh[2][KS][2], bl[2][KS][2];
    #pragma unroll
    for (int h = 0; h < 2; h++) {
        int o = 8 * h + r;
        #pragma unroll
        for (int kt = 0; kt < KS; kt++) {
            int base = (o * KS + kt) * CIN;
            #pragma unroll
            for (int p = 0; p < 2; p++) {
                float wa = wgt[base + 2 * cq + 8 * p];
                float wb = wgt[base + 2 * cq + 8 * p + 1];
                uint32_t hp = packbf(wb, wa);
                float ha = __uint_as_float(hp << 16);
                float hb = __uint_as_float(hp & 0xFFFF0000u);
                bh[h][kt][p] = hp;
                bl[h][kt][p] = packbf(wb - hb, wa - ha);
            }
        }
    }

    // ---- prologue: vectorized load of tile 0 ----
    float4 rx[4], rs;
    {
        int t = blockIdx.x;
        long long b = t >> 12, n = ((long long)(t & 4095) << 7) + 4 * q;
        #pragma unroll
        for (int cc = 0; cc < 4; cc++) {
            int c = cc * 4 + c0;
            rx[cc] = *reinterpret_cast<const float4*>(inp + (b * CIN + c) * NN + n);
        }
        rs = *reinterpret_cast<const float4*>(att + (b * KS + c0) * NN + n);
    }

    for (int i = 0; i < TILES / GRID; i++) {
        const int t = blockIdx.x + i * GRID;

        // stage tile i: conflict-free STS.128 into [c][tok] / [k][tok]
        #pragma unroll
        for (int cc = 0; cc < 4; cc++) {
            int c = cc * 4 + c0;
            *reinterpret_cast<float4*>(xs + c * PADT + 4 * q) = rx[cc];
        }
        *reinterpret_cast<float4*>(ss + c0 * PADT + 4 * q) = rs;

        // prefetch tile i+1 BEFORE the barrier (overlaps sync + compute)
        if (i + 1 < TILES / GRID) {
            int tn = t + GRID;
            long long b = tn >> 12, n = ((long long)(tn & 4095) << 7) + 4 * q;
            #pragma unroll
            for (int cc = 0; cc < 4; cc++) {
                int c = cc * 4 + c0;
                rx[cc] = *reinterpret_cast<const float4*>(inp + (b * CIN + c) * NN + n);
            }
            rs = *reinterpret_cast<const float4*>(att + (b * KS + c0) * NN + n);
        }
        __syncthreads();

        // ---- compute: each warp does 2 m16-tiles (32 tokens) ----
        #pragma unroll
        for (int mt = 0; mt < 2; mt++) {
            const int tb = w * 32 + mt * 16;
            const int tokA = tb + r, tokB = tb + r + 8;

            // x: 8 conflict-free LDS.32, packed to f32x2 pairs
            unsigned long long xA0 = pack2(xs[(2 * cq)     * PADT + tokA],
                                           xs[(2 * cq + 1) * PADT + tokA]);
            unsigned long long xA1 = pack2(xs[(2 * cq + 8) * PADT + tokA],
                                           xs[(2 * cq + 9) * PADT + tokA]);
            unsigned long long xB0 = pack2(xs[(2 * cq)     * PADT + tokB],
                                           xs[(2 * cq + 1) * PADT + tokB]);
            unsigned long long xB1 = pack2(xs[(2 * cq + 8) * PADT + tokB],
                                           xs[(2 * cq + 9) * PADT + tokB]);
            // s: broadcast LDS.32, duplicated into (s,s) u64
            unsigned long long sA[KS], sB[KS];
            #pragma unroll
            for (int k = 0; k < KS; k++) {
                float va = ss[k * PADT + tokA];
                float vb = ss[k * PADT + tokB];
                sA[k] = pack2(va, va);
                sB[k] = pack2(vb, vb);
            }

            float d0[4] = {0.f, 0.f, 0.f, 0.f};
            float d1[4] = {0.f, 0.f, 0.f, 0.f};

            #pragma unroll
            for (int kt = 0; kt < KS; kt++) {
                uint32_t ah0, al0, ah1, al1, ah2, al2, ah3, al3;
                split_z(mul2(xA0, sA[kt]), ah0, al0);
                split_z(mul2(xB0, sB[kt]), ah1, al1);
                split_z(mul2(xA1, sA[kt]), ah2, al2);
                split_z(mul2(xB1, sB[kt]), ah3, al3);

                mma_bf16(d0, ah0, ah1, ah2, ah3, bh[0][kt][0], bh[0][kt][1]);
                mma_bf16(d1, ah0, ah1, ah2, ah3, bh[1][kt][0], bh[1][kt][1]);
                mma_bf16(d0, al0, al1, al2, al3, bh[0][kt][0], bh[0][kt][1]);
                mma_bf16(d1, al0, al1, al2, al3, bh[1][kt][0], bh[1][kt][1]);
                mma_bf16(d0, ah0, ah1, ah2, ah3, bl[0][kt][0], bl[0][kt][1]);
                mma_bf16(d1, ah0, ah1, ah2, ah3, bl[1][kt][0], bl[1][kt][1]);
            }

            // epilogue: D -> od[o][tok]
            od[(2 * cq + 0) * OPAD + tokA] = d0[0];
            od[(2 * cq + 1) * OPAD + tokA] = d0[1];
            od[(2 * cq + 0) * OPAD + tokB] = d0[2];
            od[(2 * cq + 1) * OPAD + tokB] = d0[3];
            od[(8 + 2 * cq + 0) * OPAD + tokA] = d1[0];
            od[(8 + 2 * cq + 1) * OPAD + tokA] = d1[1];
            od[(8 + 2 * cq + 0) * OPAD + tokB] = d1[2];
            od[(8 + 2 * cq + 1) * OPAD + tokB] = d1[3];
        }
        __syncthreads();

        // coalesced write-out
        {
            long long b = t >> 12, n = ((long long)(t & 4095) << 7) + tid;
            float* ob = out + b * COUT * NN + n;
            #pragma unroll
            for (int o = 0; o < COUT; o++)
                ob[(long long)o * NN] = od[o * OPAD + tid];
        }
        __syncthreads();
    }
}

extern "C" void kernel_launch(void* const* d_in, const int* in_sizes, int n_in,
                              void* d_out, int out_size)
{
    const float* inp = (const float*)d_in[0];   // input  [8,16,524288]
    const float* wgt = (const float*)d_in[1];   // weight [16,4,16]
    const float* att = (const float*)d_in[2];   // attention_score [8,4,524288]
    float* out = (float*)d_out;                 // [8,16,524288]

    tconv_mma_kernel<<<GRID, THREADS>>>(inp, wgt, att, out);
}

// round 9
// speedup vs baseline: 2.4250x; 1.0144x over previous
#include <cuda_runtime.h>
#include <cstdint>

namespace {
constexpr int  CIN  = 16;
constexpr int  COUT = 16;
constexpr int  KS   = 4;
constexpr long long NN = 524288;
constexpr int  THREADS = 128;                 // 4 warps
constexpr int  TOK     = 128;                 // tokens per CTA-iter
constexpr int  TILES   = (int)(8 * NN / TOK); // 32768
constexpr int  GRID    = 8192;                // 4 tiles per CTA
constexpr int  PADT    = 132;                 // staging row pitch (floats)
}

__device__ __forceinline__ unsigned long long mul2(unsigned long long a,
                                                   unsigned long long b) {
    unsigned long long d;
    asm("mul.rn.f32x2 %0, %1, %2;" : "=l"(d) : "l"(a), "l"(b));
    return d;
}
__device__ __forceinline__ unsigned long long pack2(float lo, float hi) {
    unsigned long long d;
    asm("mov.b64 %0, {%1, %2};" : "=l"(d) : "f"(lo), "f"(hi));
    return d;
}
// pack two f32 -> bf16x2 rn. First operand = HIGH half (element 1).
__device__ __forceinline__ uint32_t packbf(float hi, float lo) {
    uint32_t r;
    asm("cvt.rn.bf16x2.f32 %0, %1, %2;" : "=r"(r) : "f"(hi), "f"(lo));
    return r;
}
// m16n8k16 row.col bf16 MMA, accumulate in place. A = weights (in regs).
__device__ __forceinline__ void mma_bf16(float* d, const uint32_t* a,
                                         uint32_t b0, uint32_t b1) {
    asm volatile(
        "mma.sync.aligned.m16n8k16.row.col.f32.bf16.bf16.f32 "
        "{%0,%1,%2,%3}, {%4,%5,%6,%7}, {%8,%9}, {%0,%1,%2,%3};"
        : "+f"(d[0]), "+f"(d[1]), "+f"(d[2]), "+f"(d[3])
        : "r"(a[0]), "r"(a[1]), "r"(a[2]), "r"(a[3]), "r"(b0), "r"(b1));
}
// split packed-f32x2 z into (zh bf16x2, zl bf16x2); element0 = low 16 bits
__device__ __forceinline__ void split_z(unsigned long long z,
                                        uint32_t& zh, uint32_t& zl) {
    float z0 = __uint_as_float((uint32_t)z);
    float z1 = __uint_as_float((uint32_t)(z >> 32));
    zh = packbf(z1, z0);
    float h0 = __uint_as_float(zh << 16);
    float h1 = __uint_as_float(zh & 0xFFFF0000u);
    zl = packbf(z1 - h1, z0 - h0);
}

__global__ __launch_bounds__(THREADS)
void tconv_mma_kernel(const float* __restrict__ inp,   // [B, CIN, N]
                      const float* __restrict__ wgt,   // [COUT, KS, CIN]
                      const float* __restrict__ att,   // [B, KS, N]
                      float* __restrict__ out)         // [B, COUT, N]
{
    // double-buffered staging: x [c][tok], s [k][tok]
    __shared__ __align__(16) float xs[2][CIN * PADT];
    __shared__ __align__(16) float ss[2][KS * PADT];

    const int tid  = threadIdx.x;
    const int lane = tid & 31;
    const int w    = tid >> 5;
    const int cq   = lane & 3;      // thread col-group
    const int r    = lane >> 2;     // thread row-group
    const int c0   = tid >> 5;      // staging channel/k group
    const int q    = lane;          // staging token quad

    // ---- W as A-fragments, built once (split hi/lo). a-reg order:
    // a0:(m=r, k=2cq..), a1:(m=r+8, k=2cq..), a2:(m=r, k=2cq+8..), a3:(m=r+8, k=2cq+8..)
    uint32_t ah[KS][4], al[KS][4];
    #pragma unroll
    for (int kt = 0; kt < KS; kt++) {
        #pragma unroll
        for (int idx = 0; idx < 4; idx++) {
            int o  = r + 8 * (idx & 1);
            int cb = 2 * cq + 8 * (idx >> 1);
            float wa = wgt[(o * KS + kt) * CIN + cb];
            float wb = wgt[(o * KS + kt) * CIN + cb + 1];
            uint32_t hp = packbf(wb, wa);
            float ha = __uint_as_float(hp << 16);
            float hb = __uint_as_float(hp & 0xFFFF0000u);
            ah[kt][idx] = hp;
            al[kt][idx] = packbf(wb - hb, wa - ha);
        }
    }

    // ---- prologue: vectorized load of tile 0 ----
    float4 rx[4], rs;
    {
        int t = blockIdx.x;
        long long b = t >> 12, n = ((long long)(t & 4095) << 7) + 4 * q;
        #pragma unroll
        for (int cc = 0; cc < 4; cc++)
            rx[cc] = *reinterpret_cast<const float4*>(inp + (b * CIN + cc * 4 + c0) * NN + n);
        rs = *reinterpret_cast<const float4*>(att + (b * KS + c0) * NN + n);
    }

    for (int i = 0; i < TILES / GRID; i++) {
        const int t = blockIdx.x + i * GRID;
        const int p = i & 1;
        float* xb = xs[p];
        float* sb = ss[p];

        // stage tile i (conflict-free STS.128)
        #pragma unroll
        for (int cc = 0; cc < 4; cc++)
            *reinterpret_cast<float4*>(xb + (cc * 4 + c0) * PADT + 4 * q) = rx[cc];
        *reinterpret_cast<float4*>(sb + c0 * PADT + 4 * q) = rs;

        // prefetch tile i+1 before the barrier
        if (i + 1 < TILES / GRID) {
            int tn = t + GRID;
            long long b = tn >> 12, n = ((long long)(tn & 4095) << 7) + 4 * q;
            #pragma unroll
            for (int cc = 0; cc < 4; cc++)
                rx[cc] = *reinterpret_cast<const float4*>(inp + (b * CIN + cc * 4 + c0) * NN + n);
            rs = *reinterpret_cast<const float4*>(att + (b * KS + c0) * NN + n);
        }
        __syncthreads();   // single barrier per tile (double-buffered)

        const long long bb = t >> 12;
        const long long n0 = ((long long)(t & 4095) << 7);
        float* ob = out + bb * COUT * NN + n0;

        // ---- compute: warp covers 32 tokens = 4 n8-tiles, interleaved in pairs
        #pragma unroll
        for (int jp = 0; jp < 2; jp++) {
            const int tb0 = w * 32 + jp * 16;
            const int tb1 = tb0 + 8;
            const int tA = tb0 + r, tB = tb1 + r;   // B-frag token = lane>>2

            // x for B-fragments: conflict-free scalar LDS, packed to f32x2
            unsigned long long xA0 = pack2(xb[(2*cq)   * PADT + tA], xb[(2*cq+1) * PADT + tA]);
            unsigned long long xA1 = pack2(xb[(2*cq+8) * PADT + tA], xb[(2*cq+9) * PADT + tA]);
            unsigned long long xB0 = pack2(xb[(2*cq)   * PADT + tB], xb[(2*cq+1) * PADT + tB]);
            unsigned long long xB1 = pack2(xb[(2*cq+8) * PADT + tB], xb[(2*cq+9) * PADT + tB]);

            float dA[4] = {0.f, 0.f, 0.f, 0.f};
            float dB[4] = {0.f, 0.f, 0.f, 0.f};

            #pragma unroll
            for (int kt = 0; kt < KS; kt++) {
                float sa = sb[kt * PADT + tA];
                float sv = sb[kt * PADT + tB];
                unsigned long long sda = pack2(sa, sa);
                unsigned long long sdb = pack2(sv, sv);

                uint32_t bA0h, bA0l, bA1h, bA1l, bB0h, bB0l, bB1h, bB1l;
                split_z(mul2(xA0, sda), bA0h, bA0l);
                split_z(mul2(xA1, sda), bA1h, bA1l);
                split_z(mul2(xB0, sdb), bB0h, bB0l);
                split_z(mul2(xB1, sdb), bB1h, bB1l);

                mma_bf16(dA, ah[kt], bA0h, bA1h);
                mma_bf16(dB, ah[kt], bB0h, bB1h);
                mma_bf16(dA, ah[kt], bA0l, bA1l);
                mma_bf16(dB, ah[kt], bB0l, bB1l);
                mma_bf16(dA, al[kt], bA0h, bA1h);
                mma_bf16(dB, al[kt], bB0h, bB1h);
            }

            // direct stores: d0,d1 = Y[o=r][tb+2cq, tb+2cq+1]; d2,d3 = o=r+8
            *reinterpret_cast<float2*>(ob + (long long)r       * NN + tb0 + 2*cq) = make_float2(dA[0], dA[1]);
            *reinterpret_cast<float2*>(ob + (long long)(r + 8) * NN + tb0 + 2*cq) = make_float2(dA[2], dA[3]);
            *reinterpret_cast<float2*>(ob + (long long)r       * NN + tb1 + 2*cq) = make_float2(dB[0], dB[1]);
            *reinterpret_cast<float2*>(ob + (long long)(r + 8) * NN + tb1 + 2*cq) = make_float2(dB[2], dB[3]);
        }
    }
}

extern "C" void kernel_launch(void* const* d_in, const int* in_sizes, int n_in,
                              void* d_out, int out_size)
{
    const float* inp = (const float*)d_in[0];   // input  [8,16,524288]
    const float* wgt = (const float*)d_in[1];   // weight [16,4,16]
    const float* att = (const float*)d_in[2];   // attention_score [8,4,524288]
    float* out = (float*)d_out;                 // [8,16,524288]

    tconv_mma_kernel<<<GRID, THREADS>>>(inp, wgt, att, out);
}